// round 10
// baseline (speedup 1.0000x reference)
#include <cuda_runtime.h>
#include <cuda_bf16.h>
#include <math.h>
#include <stdint.h>

// TopkRouter: logits = X @ W^T + b ; top-8 ; masked softmax.
// X: [32768, 2048] f32, W: [64, 2048] f32, b: [64] f32
// out: probs [32768, 64] f32 then indices [32768, 8] (as f32).
//
// Numerics (FROZEN, matches XLA:CPU Eigen gebp bitwise): per output, serial
// ascending-k fp32 FMA within 320-wide K panels; master += panel at each
// boundary (k=320,...,1920); 128-wide remainder; bias added at the end.
//
// R10: 128-thread CTAs, 8 tokens x 8 experts per thread (2x arithmetic
// intensity per LDS), master accumulator in smem (= logits buffer, scalar
// flush at panel boundaries), no launch_bounds reg cap, X via cp.async
// double-buffered, W reg-prefetch, WS_STRIDE 72.

#define TOKENS 32768
#define EMBED 2048
#define NEXP 64
#define TOPK 8
#define TPB 128          // tokens per block
#define NTHREADS 128
#define KT 32            // k tile
#define NTILES (EMBED / KT)
#define KC_TILES 10      // flush every 10 tiles => panel = 320 (Eigen cap)
#define XS_STRIDE 36     // 16B-aligned rows (cp.async dst)
#define WS_STRIDE 72     // transposed W rows, 16B-aligned, low-conflict stores
#define LG_STRIDE 65     // logits row stride (conflict-free scans)

// dynamic smem layout (floats)
#define XBUF0 0
#define XBUF1 4608                    // 128*36
#define WBUF0 9216
#define WBUF1 11520                   // +32*72
#define LOG_OFF 13824
#define SIDX_OFF 22144                // +128*65
#define SBIAS_OFF 23168
#define SMEM_FLOATS 23232             // 92928 bytes

static __device__ __forceinline__ unsigned long long pack2(float x) {
    unsigned long long r;
    asm("mov.b64 %0, {%1, %1};" : "=l"(r) : "f"(x));
    return r;
}
static __device__ __forceinline__ unsigned long long ffma2(unsigned long long a,
                                                           unsigned long long b,
                                                           unsigned long long c) {
    unsigned long long d;
    asm("fma.rn.f32x2 %0, %1, %2, %3;" : "=l"(d) : "l"(a), "l"(b), "l"(c));
    return d;
}
static __device__ __forceinline__ void unpack2(unsigned long long v, float& lo, float& hi) {
    asm("mov.b64 {%0, %1}, %2;" : "=f"(lo), "=f"(hi) : "l"(v));
}
static __device__ __forceinline__ void cp_async16(uint32_t saddr, const void* g) {
    asm volatile("cp.async.cg.shared.global [%0], [%1], 16;" :: "r"(saddr), "l"(g));
}
static __device__ __forceinline__ void cp_commit() {
    asm volatile("cp.async.commit_group;" ::: "memory");
}
static __device__ __forceinline__ void cp_wait0() {
    asm volatile("cp.async.wait_group 0;" ::: "memory");
}

__global__ void topk_router_kernel(const float* __restrict__ X,
                                   const float* __restrict__ W,
                                   const float* __restrict__ B,
                                   float* __restrict__ probs_out,
                                   float* __restrict__ idx_out) {
    extern __shared__ float smem[];
    float* logits = smem + LOG_OFF;   // doubles as master accumulator
    float* sidx   = smem + SIDX_OFF;
    float* sbias  = smem + SBIAS_OFF;

    const int tid  = threadIdx.x;
    const int tok0 = blockIdx.x * TPB;

    if (tid < NEXP) sbias[tid] = B[tid];
    // zero master accumulator (covered by tile barriers before first flush)
    for (int i = tid; i < TPB * LG_STRIDE; i += NTHREADS) logits[i] = 0.0f;

    const int g = tid >> 3;   // 0..15 ; tokens g + 16*i (i=0..7)
    const int h = tid & 7;    // experts 4h..4h+3 and 32+4h..32+4h+3

    // loader lanes
    const int lr = tid >> 3;          // row base (0..15)
    const int lc = tid & 7;           // 4-float chunk
    const float* Xg = X + (size_t)(tok0 + lr) * EMBED + 4 * lc;
    const float* Wg = W + (size_t)lr * EMBED + 4 * lc;   // rows lr+16r

    const uint32_t smem_base_b = (uint32_t)__cvta_generic_to_shared(smem);

    // per-output panel accumulators (registers)
    unsigned long long til[8][4];
#pragma unroll
    for (int i = 0; i < 8; i++)
#pragma unroll
        for (int j = 0; j < 4; j++) til[i][j] = 0ull;

    float4 wr_[4];

    // prologue: async-load X tile 0, LDG W tile 0
#pragma unroll
    for (int r = 0; r < 8; r++) {
        uint32_t dst = smem_base_b + 4u * (XBUF0 + (uint32_t)(lr + 16 * r) * XS_STRIDE + 4 * lc);
        cp_async16(dst, Xg + (size_t)(16 * r) * EMBED);
    }
    cp_commit();
#pragma unroll
    for (int r = 0; r < 4; r++)
        wr_[r] = *reinterpret_cast<const float4*>(Wg + (size_t)(16 * r) * EMBED);

    for (int t = 0; t < NTILES; t++) {
        const int buf = t & 1;
        float* Xs = smem + (buf ? XBUF1 : XBUF0);
        float* Ws = smem + (buf ? WBUF1 : WBUF0);

        // store W tile t (transposed) into this tile's buffer
#pragma unroll
        for (int r = 0; r < 4; r++) {
            int e = lr + 16 * r;
            Ws[(4 * lc + 0) * WS_STRIDE + e] = wr_[r].x;
            Ws[(4 * lc + 1) * WS_STRIDE + e] = wr_[r].y;
            Ws[(4 * lc + 2) * WS_STRIDE + e] = wr_[r].z;
            Ws[(4 * lc + 3) * WS_STRIDE + e] = wr_[r].w;
        }

        cp_wait0();
        __syncthreads();      // tile t fully visible; tile t-1 compute done

        // issue next tile's loads (hidden under compute of tile t)
        if (t + 1 < NTILES) {
            const float* Xn = Xg + (size_t)(t + 1) * KT;
            const float* Wn = Wg + (size_t)(t + 1) * KT;
            const uint32_t xb = (t + 1) & 1 ? XBUF1 : XBUF0;
#pragma unroll
            for (int r = 0; r < 8; r++) {
                uint32_t dst = smem_base_b + 4u * (xb + (uint32_t)(lr + 16 * r) * XS_STRIDE + 4 * lc);
                cp_async16(dst, Xn + (size_t)(16 * r) * EMBED);
            }
            cp_commit();
#pragma unroll
            for (int r = 0; r < 4; r++)
                wr_[r] = *reinterpret_cast<const float4*>(Wn + (size_t)(16 * r) * EMBED);
        }

        // ---- compute: serial ascending k (order frozen) ----
#pragma unroll 4
        for (int kk2 = 0; kk2 < KT; kk2 += 2) {
            // X: one LDS.64 per token covering k, k+1 (banks 4g+c: conflict-free)
            float2 xv[8];
#pragma unroll
            for (int i = 0; i < 8; i++)
                xv[i] = *reinterpret_cast<const float2*>(Xs + (g + 16 * i) * XS_STRIDE + kk2);
#pragma unroll
            for (int u = 0; u < 2; u++) {
                const float* wrow = Ws + (kk2 + u) * WS_STRIDE;
                ulonglong2 wa = *reinterpret_cast<const ulonglong2*>(wrow + 4 * h);
                ulonglong2 wb = *reinterpret_cast<const ulonglong2*>(wrow + 32 + 4 * h);
#pragma unroll
                for (int i = 0; i < 8; i++) {
                    unsigned long long xx = pack2(u == 0 ? xv[i].x : xv[i].y);
                    til[i][0] = ffma2(xx, wa.x, til[i][0]);
                    til[i][1] = ffma2(xx, wa.y, til[i][1]);
                    til[i][2] = ffma2(xx, wb.x, til[i][2]);
                    til[i][3] = ffma2(xx, wb.y, til[i][3]);
                }
            }
        }

        // ---- Eigen panel boundary (k=320,640,...,1920): master += panel ----
        if ((t + 1) % KC_TILES == 0) {
#pragma unroll
            for (int i = 0; i < 8; i++) {
                float* row = logits + (g + 16 * i) * LG_STRIDE;
#pragma unroll
                for (int j = 0; j < 4; j++) {
                    float lo, hi;
                    unpack2(til[i][j], lo, hi);
                    int e = (j < 2) ? (4 * h + 2 * j) : (32 + 4 * h + 2 * (j - 2));
                    row[e]     = row[e]     + lo;
                    row[e + 1] = row[e + 1] + hi;
                    til[i][j] = 0ull;
                }
            }
        }
    }

    // final remainder panel (k = 1920..2047) + bias
    __syncthreads();
#pragma unroll
    for (int i = 0; i < 8; i++) {
        float* row = logits + (g + 16 * i) * LG_STRIDE;
#pragma unroll
        for (int j = 0; j < 4; j++) {
            float lo, hi;
            unpack2(til[i][j], lo, hi);
            int e = (j < 2) ? (4 * h + 2 * j) : (32 + 4 * h + 2 * (j - 2));
            row[e]     = (row[e]     + lo) + sbias[e];
            row[e + 1] = (row[e + 1] + hi) + sbias[e + 1];
        }
    }
    __syncthreads();

    // ---- top-8 + masked softmax, one thread per token ----
    {
        float* row = logits + tid * LG_STRIDE;
        float vals[TOPK];
        int   inds[TOPK];
#pragma unroll
        for (int s = 0; s < TOPK; s++) {
            float best = -INFINITY;
            int bi = 0;
            for (int j = 0; j < NEXP; j++) {
                float v = row[j];
                if (v > best) { best = v; bi = j; }   // strict > : lowest index wins ties
            }
            vals[s] = best;
            inds[s] = bi;
            row[bi] = -INFINITY;
        }
        float m = vals[0];
        float e[TOPK];
        float sum = 0.0f;
#pragma unroll
        for (int s = 0; s < TOPK; s++) { e[s] = expf(vals[s] - m); sum += e[s]; }
        float inv = 1.0f / sum;
        for (int j = 0; j < NEXP; j++) row[j] = 0.0f;
#pragma unroll
        for (int s = 0; s < TOPK; s++) {
            row[inds[s]] = e[s] * inv;
            sidx[tid * TOPK + s] = (float)inds[s];
        }
    }
    __syncthreads();

    // ---- coalesced writes ----
    for (int i = tid; i < TPB * NEXP; i += NTHREADS) {
        int t = i >> 6;
        int e = i & 63;
        probs_out[(size_t)(tok0 + t) * NEXP + e] = logits[t * LG_STRIDE + e];
    }
    if (idx_out) {
        for (int i = tid; i < TPB * TOPK; i += NTHREADS) {
            idx_out[(size_t)tok0 * TOPK + i] = sidx[i];
        }
    }
}

extern "C" void kernel_launch(void* const* d_in, const int* in_sizes, int n_in,
                              void* d_out, int out_size) {
    const float* X = (const float*)d_in[0];
    const float* W = (const float*)d_in[1];
    const float* B = (const float*)d_in[2];
    float* out = (float*)d_out;

    const long long PROBS_ELEMS = (long long)TOKENS * NEXP;   // 2097152
    const long long IDX_ELEMS   = (long long)TOKENS * TOPK;   // 262144
    float* idx_out = nullptr;
    if ((long long)out_size >= PROBS_ELEMS + IDX_ELEMS) idx_out = out + PROBS_ELEMS;

    const int smem_bytes = SMEM_FLOATS * 4;
    cudaFuncSetAttribute(topk_router_kernel,
                         cudaFuncAttributeMaxDynamicSharedMemorySize, smem_bytes);
    topk_router_kernel<<<TOKENS / TPB, NTHREADS, smem_bytes>>>(X, W, B, out, idx_out);
}

// round 11
// speedup vs baseline: 1.0040x; 1.0040x over previous
#include <cuda_runtime.h>
#include <cuda_bf16.h>
#include <math.h>
#include <stdint.h>

// TopkRouter: logits = X @ W^T + b ; top-8 ; masked softmax.
// X: [32768, 2048] f32, W: [64, 2048] f32, b: [64] f32
// out: probs [32768, 64] f32 then indices [32768, 8] (as f32).
//
// Numerics (FROZEN, matches XLA:CPU Eigen gebp bitwise): per output, serial
// ascending-k fp32 FMA within 320-wide K panels; master += panel at each
// boundary (k=320,...,1920); 128-wide remainder; bias added at the end.
//
// R11: 256 threads, 128 tokens/CTA (2 CTA/SM, 16 warps), KT=64 (half the
// barriers), X via cp.async double-buffered + LDS.64 k-pair reads, W loader
// remapped for 2-way STS conflicts, frozen Eigen-320 panel accumulation.

#define TOKENS 32768
#define EMBED 2048
#define NEXP 64
#define TOPK 8
#define TPB 128          // tokens per block
#define NTHREADS 256
#define KT 64            // k tile
#define NTILES (EMBED / KT)          // 32
#define KC_TILES 5       // flush every 5 tiles => panel = 320 (Eigen cap)
#define XS_STRIDE 68     // 16B-aligned rows; LDS.64 reads conflict-free
#define WS_STRIDE 72     // transposed W rows; 2-way STS, broadcast-clean reads
#define LG_STRIDE 65     // logits row stride

// dynamic smem layout (floats)
#define XBUF0 0                        // 128*68 = 8704
#define XBUF1 8704
#define WBUF0 17408                    // 64*72 = 4608
#define WBUF1 22016
#define SIDX_OFF 26624                 // 128*8
#define SBIAS_OFF 27648                // 64
#define SMEM_FLOATS 27712              // 110848 bytes/CTA -> 2 CTA/SM

static __device__ __forceinline__ unsigned long long pack2(float x) {
    unsigned long long r;
    asm("mov.b64 %0, {%1, %1};" : "=l"(r) : "f"(x));
    return r;
}
static __device__ __forceinline__ unsigned long long ffma2(unsigned long long a,
                                                           unsigned long long b,
                                                           unsigned long long c) {
    unsigned long long d;
    asm("fma.rn.f32x2 %0, %1, %2, %3;" : "=l"(d) : "l"(a), "l"(b), "l"(c));
    return d;
}
static __device__ __forceinline__ unsigned long long fadd2(unsigned long long a,
                                                           unsigned long long b) {
    unsigned long long d;
    asm("add.rn.f32x2 %0, %1, %2;" : "=l"(d) : "l"(a), "l"(b));
    return d;
}
static __device__ __forceinline__ void unpack2(unsigned long long v, float& lo, float& hi) {
    asm("mov.b64 {%0, %1}, %2;" : "=f"(lo), "=f"(hi) : "l"(v));
}
static __device__ __forceinline__ void cp_async16(uint32_t saddr, const void* g) {
    asm volatile("cp.async.cg.shared.global [%0], [%1], 16;" :: "r"(saddr), "l"(g));
}
static __device__ __forceinline__ void cp_commit() {
    asm volatile("cp.async.commit_group;" ::: "memory");
}
static __device__ __forceinline__ void cp_wait0() {
    asm volatile("cp.async.wait_group 0;" ::: "memory");
}

__global__ __launch_bounds__(NTHREADS, 2)
void topk_router_kernel(const float* __restrict__ X,
                        const float* __restrict__ W,
                        const float* __restrict__ B,
                        float* __restrict__ probs_out,
                        float* __restrict__ idx_out) {
    extern __shared__ float smem[];
    float* logits = smem;             // reuses XBUF0 after GEMM (8320 <= 8704)
    float* sidx   = smem + SIDX_OFF;
    float* sbias  = smem + SBIAS_OFF;

    const int tid  = threadIdx.x;
    const int tok0 = blockIdx.x * TPB;

    if (tid < NEXP) sbias[tid] = B[tid];

    const int g = tid >> 3;   // token group: tokens 4g..4g+3
    const int h = tid & 7;    // experts 4h..4h+3 and 32+4h..32+4h+3

    // X loader lanes: 128 tokens x 16 chunks; rows xt+16r (r=0..7)
    const int xt = tid >> 4;          // 0..15
    const int xc = tid & 15;          // float4 chunk 0..15
    const float* Xg = X + (size_t)(tok0 + xt) * EMBED + 4 * xc;
    // W loader lanes: 64 rows x 16 chunks; rows wt+16r (r=0..3)
    const int wt = tid & 15;          // row base
    const int wc = tid >> 4;          // chunk 0..15
    const float* Wg = W + (size_t)wt * EMBED + 4 * wc;

    const uint32_t smem_base_b = (uint32_t)__cvta_generic_to_shared(smem);

    // accumulators: til (panel), mst (master) — frozen two-level order
    unsigned long long mst[4][4];
    unsigned long long til[4][4];
#pragma unroll
    for (int i = 0; i < 4; i++)
#pragma unroll
        for (int j = 0; j < 4; j++) { mst[i][j] = 0ull; til[i][j] = 0ull; }

    float4 wr_[4];

    // prologue: async-load X tile 0, LDG W tile 0
#pragma unroll
    for (int r = 0; r < 8; r++) {
        uint32_t dst = smem_base_b + 4u * (XBUF0 + (uint32_t)(xt + 16 * r) * XS_STRIDE + 4 * xc);
        cp_async16(dst, Xg + (size_t)(16 * r) * EMBED);
    }
    cp_commit();
#pragma unroll
    for (int r = 0; r < 4; r++)
        wr_[r] = *reinterpret_cast<const float4*>(Wg + (size_t)(16 * r) * EMBED);

    for (int t = 0; t < NTILES; t++) {
        const int buf = t & 1;
        float* Xs = smem + (buf ? XBUF1 : XBUF0);
        float* Ws = smem + (buf ? WBUF1 : WBUF0);

        // store W tile t (transposed; 2-way conflicts)
#pragma unroll
        for (int r = 0; r < 4; r++) {
            int e = wt + 16 * r;
            Ws[(4 * wc + 0) * WS_STRIDE + e] = wr_[r].x;
            Ws[(4 * wc + 1) * WS_STRIDE + e] = wr_[r].y;
            Ws[(4 * wc + 2) * WS_STRIDE + e] = wr_[r].z;
            Ws[(4 * wc + 3) * WS_STRIDE + e] = wr_[r].w;
        }

        cp_wait0();
        __syncthreads();      // tile t visible everywhere; tile t-1 compute done

        // issue next tile's loads (hidden under compute of tile t)
        if (t + 1 < NTILES) {
            const float* Xn = Xg + (size_t)(t + 1) * KT;
            const float* Wn = Wg + (size_t)(t + 1) * KT;
            const uint32_t xb = ((t + 1) & 1) ? XBUF1 : XBUF0;
#pragma unroll
            for (int r = 0; r < 8; r++) {
                uint32_t dst = smem_base_b + 4u * (xb + (uint32_t)(xt + 16 * r) * XS_STRIDE + 4 * xc);
                cp_async16(dst, Xn + (size_t)(16 * r) * EMBED);
            }
            cp_commit();
#pragma unroll
            for (int r = 0; r < 4; r++)
                wr_[r] = *reinterpret_cast<const float4*>(Wn + (size_t)(16 * r) * EMBED);
        }

        // ---- compute: serial ascending k (order frozen) ----
#pragma unroll 8
        for (int kk2 = 0; kk2 < KT; kk2 += 2) {
            // X: LDS.64 per token covering k,k+1 (banks 4*dt distinct, 8-way bcast)
            float2 xv0 = *reinterpret_cast<const float2*>(Xs + (4 * g + 0) * XS_STRIDE + kk2);
            float2 xv1 = *reinterpret_cast<const float2*>(Xs + (4 * g + 1) * XS_STRIDE + kk2);
            float2 xv2 = *reinterpret_cast<const float2*>(Xs + (4 * g + 2) * XS_STRIDE + kk2);
            float2 xv3 = *reinterpret_cast<const float2*>(Xs + (4 * g + 3) * XS_STRIDE + kk2);
#pragma unroll
            for (int u = 0; u < 2; u++) {
                const float* wrow = Ws + (kk2 + u) * WS_STRIDE;
                ulonglong2 wa = *reinterpret_cast<const ulonglong2*>(wrow + 4 * h);
                ulonglong2 wb = *reinterpret_cast<const ulonglong2*>(wrow + 32 + 4 * h);
                unsigned long long xx0 = pack2(u == 0 ? xv0.x : xv0.y);
                unsigned long long xx1 = pack2(u == 0 ? xv1.x : xv1.y);
                unsigned long long xx2 = pack2(u == 0 ? xv2.x : xv2.y);
                unsigned long long xx3 = pack2(u == 0 ? xv3.x : xv3.y);
                til[0][0] = ffma2(xx0, wa.x, til[0][0]);
                til[0][1] = ffma2(xx0, wa.y, til[0][1]);
                til[0][2] = ffma2(xx0, wb.x, til[0][2]);
                til[0][3] = ffma2(xx0, wb.y, til[0][3]);
                til[1][0] = ffma2(xx1, wa.x, til[1][0]);
                til[1][1] = ffma2(xx1, wa.y, til[1][1]);
                til[1][2] = ffma2(xx1, wb.x, til[1][2]);
                til[1][3] = ffma2(xx1, wb.y, til[1][3]);
                til[2][0] = ffma2(xx2, wa.x, til[2][0]);
                til[2][1] = ffma2(xx2, wa.y, til[2][1]);
                til[2][2] = ffma2(xx2, wb.x, til[2][2]);
                til[2][3] = ffma2(xx2, wb.y, til[2][3]);
                til[3][0] = ffma2(xx3, wa.x, til[3][0]);
                til[3][1] = ffma2(xx3, wa.y, til[3][1]);
                til[3][2] = ffma2(xx3, wb.x, til[3][2]);
                til[3][3] = ffma2(xx3, wb.y, til[3][3]);
            }
        }

        // ---- Eigen panel boundary (k=320,640,...,1920) ----
        if ((t + 1) % KC_TILES == 0) {
#pragma unroll
            for (int i = 0; i < 4; i++)
#pragma unroll
                for (int j = 0; j < 4; j++) {
                    mst[i][j] = fadd2(mst[i][j], til[i][j]);
                    til[i][j] = 0ull;
                }
        }
    }
    // final remainder panel (k = 1920..2047)
#pragma unroll
    for (int i = 0; i < 4; i++)
#pragma unroll
        for (int j = 0; j < 4; j++) mst[i][j] = fadd2(mst[i][j], til[i][j]);

    __syncthreads();   // tiles dead; reuse smem for logits

    // ---- bias add + stash logits ----
#pragma unroll
    for (int i = 0; i < 4; i++) {
        int t = 4 * g + i;
#pragma unroll
        for (int j = 0; j < 4; j++) {
            int e = (j < 2) ? (4 * h + 2 * j) : (32 + 4 * h + 2 * (j - 2));
            float lo, hi;
            unpack2(mst[i][j], lo, hi);
            logits[t * LG_STRIDE + e]     = lo + sbias[e];
            logits[t * LG_STRIDE + e + 1] = hi + sbias[e + 1];
        }
    }
    __syncthreads();

    // ---- top-8 + masked softmax, one thread per token ----
    if (tid < TPB) {
        float* row = logits + tid * LG_STRIDE;
        float vals[TOPK];
        int   inds[TOPK];
#pragma unroll
        for (int s = 0; s < TOPK; s++) {
            float best = -INFINITY;
            int bi = 0;
            for (int j = 0; j < NEXP; j++) {
                float v = row[j];
                if (v > best) { best = v; bi = j; }   // strict > : lowest index wins ties
            }
            vals[s] = best;
            inds[s] = bi;
            row[bi] = -INFINITY;
        }
        float m = vals[0];
        float e[TOPK];
        float sum = 0.0f;
#pragma unroll
        for (int s = 0; s < TOPK; s++) { e[s] = expf(vals[s] - m); sum += e[s]; }
        float inv = 1.0f / sum;
        for (int j = 0; j < NEXP; j++) row[j] = 0.0f;
#pragma unroll
        for (int s = 0; s < TOPK; s++) {
            row[inds[s]] = e[s] * inv;
            sidx[tid * TOPK + s] = (float)inds[s];
        }
    }
    __syncthreads();

    // ---- coalesced writes ----
    for (int i = tid; i < TPB * NEXP; i += NTHREADS) {
        int t = i >> 6;
        int e = i & 63;
        probs_out[(size_t)(tok0 + t) * NEXP + e] = logits[t * LG_STRIDE + e];
    }
    if (idx_out) {
        for (int i = tid; i < TPB * TOPK; i += NTHREADS) {
            idx_out[(size_t)tok0 * TOPK + i] = sidx[i];
        }
    }
}

extern "C" void kernel_launch(void* const* d_in, const int* in_sizes, int n_in,
                              void* d_out, int out_size) {
    const float* X = (const float*)d_in[0];
    const float* W = (const float*)d_in[1];
    const float* B = (const float*)d_in[2];
    float* out = (float*)d_out;

    const long long PROBS_ELEMS = (long long)TOKENS * NEXP;   // 2097152
    const long long IDX_ELEMS   = (long long)TOKENS * TOPK;   // 262144
    float* idx_out = nullptr;
    if ((long long)out_size >= PROBS_ELEMS + IDX_ELEMS) idx_out = out + PROBS_ELEMS;

    const int smem_bytes = SMEM_FLOATS * 4;
    cudaFuncSetAttribute(topk_router_kernel,
                         cudaFuncAttributeMaxDynamicSharedMemorySize, smem_bytes);
    topk_router_kernel<<<TOKENS / TPB, NTHREADS, smem_bytes>>>(X, W, B, out, idx_out);
}